// round 2
// baseline (speedup 1.0000x reference)
#include <cuda_runtime.h>

#define FULL_MASK 0xFFFFFFFFu

constexpr int H = 512;
constexpr int W = 512;
constexpr int NPLANE = 8 * 16;            // 128 independent (B,C) planes
constexpr int STRIP_OUT = 60;             // useful output columns per warp (2 cols/lane, lanes 1..30)
constexpr int NSTRIP = (W + STRIP_OUT - 1) / STRIP_OUT;   // 9
constexpr int SEG = 64;                   // output rows per warp task
constexpr int NSEG = H / SEG;             // 8
constexpr int WARPS_PER_BLOCK = 4;
constexpr int NTASK = NPLANE * NSTRIP * NSEG;             // 9216
constexpr int NBLOCK = NTASK / WARPS_PER_BLOCK;           // 2304

__global__ void __launch_bounds__(WARPS_PER_BLOCK * 32)
guided_filter_kernel(const float* __restrict__ gI,
                     const float* __restrict__ gP,
                     float* __restrict__ gO)
{
    const int lane = threadIdx.x & 31;
    const int task = blockIdx.x * WARPS_PER_BLOCK + (threadIdx.x >> 5);

    const int pl  = task / (NSTRIP * NSEG);
    const int rem = task - pl * (NSTRIP * NSEG);
    const int sx  = rem / NSEG;
    const int sy  = rem - sx * NSEG;

    // Each lane owns two adjacent columns x0, x1. Lane 0 / lane 31 are halo.
    const int xb = sx * STRIP_OUT - 2;
    const int x0 = xb + 2 * lane;
    const int x1 = x0 + 1;
    const bool in0 = ((unsigned)x0 < (unsigned)W);
    const bool in1 = ((unsigned)x1 < (unsigned)W);
    const bool vec_ok = (x0 >= 0) && (x1 < W);

    const size_t pbase = (size_t)pl * (size_t)(H * W);
    const float* baseI = gI + pbase;
    const float* baseP = gP + pbase;
    float*       baseO = gO + pbase;

    // Horizontal window counts (count_include_pad=False): 3 interior, 2 at edges
    const float cx0 = (x0 >= 1 && x0 <= W - 2) ? 3.0f : 2.0f;
    const float cx1 = (x1 >= 1 && x1 <= W - 2) ? 3.0f : 2.0f;
    const float inv3_0 = 1.0f / (3.0f * cx0);
    const float inv3_1 = 1.0f / (3.0f * cx1);
    const float inv2_0 = 1.0f / (2.0f * cx0);
    const float inv2_1 = 1.0f / (2.0f * cx1);

    const int r0 = sy * SEG;

    // Register rings, period 3, index 2 = newest row. Two columns per entry.
    float hI0x = 0.f, hI0y = 0.f, hI1x = 0.f, hI1y = 0.f, hI2x = 0.f, hI2y = 0.f;
    float hP0x = 0.f, hP0y = 0.f, hP1x = 0.f, hP1y = 0.f, hP2x = 0.f, hP2y = 0.f;
    float hII0x = 0.f, hII0y = 0.f, hII1x = 0.f, hII1y = 0.f, hII2x = 0.f, hII2y = 0.f;
    float hIP0x = 0.f, hIP0y = 0.f, hIP1x = 0.f, hIP1y = 0.f, hIP2x = 0.f, hIP2y = 0.f;
    float hA0x = 0.f, hA0y = 0.f, hA1x = 0.f, hA1y = 0.f, hA2x = 0.f, hA2y = 0.f;
    float hB0x = 0.f, hB0y = 0.f, hB1x = 0.f, hB1y = 0.f, hB2x = 0.f, hB2y = 0.f;
    float I0x = 0.f, I0y = 0.f, I1x = 0.f, I1y = 0.f, I2x = 0.f, I2y = 0.f;

    // step 1: load row y, build horizontal 1x3 sums (new in slot 2)
    auto step_load = [&](int it) {
        const int y = r0 - 2 + it;
        hI0x = hI1x;  hI0y = hI1y;  hI1x = hI2x;  hI1y = hI2y;
        hP0x = hP1x;  hP0y = hP1y;  hP1x = hP2x;  hP1y = hP2y;
        hII0x = hII1x; hII0y = hII1y; hII1x = hII2x; hII1y = hII2y;
        hIP0x = hIP1x; hIP0y = hIP1y; hIP1x = hIP2x; hIP1y = hIP2y;
        I0x = I1x; I0y = I1y; I1x = I2x; I1y = I2y;

        float Iv0 = 0.f, Iv1 = 0.f, Pv0 = 0.f, Pv1 = 0.f;
        if ((unsigned)y < (unsigned)H) {
            const size_t off = (size_t)y * W + x0;
            if (vec_ok) {
                const float2 ti = *reinterpret_cast<const float2*>(baseI + off);
                const float2 tp = *reinterpret_cast<const float2*>(baseP + off);
                Iv0 = ti.x; Iv1 = ti.y; Pv0 = tp.x; Pv1 = tp.y;
            } else {
                if (in0) { Iv0 = baseI[off];     Pv0 = baseP[off]; }
                if (in1) { Iv1 = baseI[off + 1]; Pv1 = baseP[off + 1]; }
            }
        }
        // neighbors across lanes: left of x0 = prev lane's x1; right of x1 = next lane's x0
        const float Il = __shfl_up_sync(FULL_MASK, Iv1, 1);
        const float Ir = __shfl_down_sync(FULL_MASK, Iv0, 1);
        const float Pl = __shfl_up_sync(FULL_MASK, Pv1, 1);
        const float Pr = __shfl_down_sync(FULL_MASK, Pv0, 1);

        const float sI  = Iv0 + Iv1;
        const float sP  = Pv0 + Pv1;
        const float sII = Iv0 * Iv0 + Iv1 * Iv1;
        const float sIP = Iv0 * Pv0 + Iv1 * Pv1;

        hI2x  = Il + sI;             hI2y  = sI + Ir;
        hP2x  = Pl + sP;             hP2y  = sP + Pr;
        hII2x = fmaf(Il, Il, sII);   hII2y = fmaf(Ir, Ir, sII);
        hIP2x = fmaf(Il, Pl, sIP);   hIP2y = fmaf(Ir, Pr, sIP);
        I2x = Iv0; I2y = Iv1;
    };

    // step 2: 3x3 means at row y-1 -> a,b, then their horizontal 1x3 sums
    auto step_ab = [&](int it) {
        const int ry = (r0 - 2 + it) - 1;
        const bool yint = (ry >= 1 && ry <= H - 2);
        const bool yin  = ((unsigned)ry < (unsigned)H);
        const float ic0 = yint ? inv3_0 : inv2_0;
        const float ic1 = yint ? inv3_1 : inv2_1;

        const float mI0  = (hI0x  + hI1x  + hI2x ) * ic0;
        const float mP0  = (hP0x  + hP1x  + hP2x ) * ic0;
        const float mII0 = (hII0x + hII1x + hII2x) * ic0;
        const float mIP0 = (hIP0x + hIP1x + hIP2x) * ic0;
        const float mI1  = (hI0y  + hI1y  + hI2y ) * ic1;
        const float mP1  = (hP0y  + hP1y  + hP2y ) * ic1;
        const float mII1 = (hII0y + hII1y + hII2y) * ic1;
        const float mIP1 = (hIP0y + hIP1y + hIP2y) * ic1;

        float a0 = __fdividef(mIP0 - mI0 * mP0, (mII0 - mI0 * mI0) + 0.01f);
        float b0 = mP0 - a0 * mI0;
        float a1 = __fdividef(mIP1 - mI1 * mP1, (mII1 - mI1 * mI1) + 0.01f);
        float b1 = mP1 - a1 * mI1;
        // out-of-image positions contribute ZERO to the a/b blur
        if (!(in0 && yin)) { a0 = 0.f; b0 = 0.f; }
        if (!(in1 && yin)) { a1 = 0.f; b1 = 0.f; }

        const float al = __shfl_up_sync(FULL_MASK, a1, 1);
        const float ar = __shfl_down_sync(FULL_MASK, a0, 1);
        const float bl = __shfl_up_sync(FULL_MASK, b1, 1);
        const float br = __shfl_down_sync(FULL_MASK, b0, 1);

        hA0x = hA1x; hA0y = hA1y; hA1x = hA2x; hA1y = hA2y;
        hB0x = hB1x; hB0y = hB1y; hB1x = hB2x; hB1y = hB2y;
        const float sA = a0 + a1;
        const float sB = b0 + b1;
        hA2x = al + sA; hA2y = sA + ar;
        hB2x = bl + sB; hB2y = sB + br;
    };

    // step 3: 3x3 blur of a,b at row y-2, write output
    auto step_out = [&](int it) {
        const int ro = (r0 - 2 + it) - 2;
        const bool yint = (ro >= 1 && ro <= H - 2);
        const float io0 = yint ? inv3_0 : inv2_0;
        const float io1 = yint ? inv3_1 : inv2_1;
        const float mA0 = (hA0x + hA1x + hA2x) * io0;
        const float mB0 = (hB0x + hB1x + hB2x) * io0;
        const float mA1 = (hA0y + hA1y + hA2y) * io1;
        const float mB1 = (hB0y + hB1y + hB2y) * io1;
        float2 o;
        o.x = mA0 * I0x + mB0;    // I0x/I0y hold raw I at row ro
        o.y = mA1 * I0y + mB1;
        if (lane >= 1 && lane <= 30 && x0 < W) {
            *reinterpret_cast<float2*>(baseO + (size_t)ro * W + x0) = o;
        }
    };

    // prologue: prime rings on rows r0-2 .. r0+1
#pragma unroll
    for (int it = 0; it < 4; ++it) {
        step_load(it);
        if (it >= 2) step_ab(it);
    }
    // steady state: unroll 3 matches the ring period -> rotation by renaming
#pragma unroll 3
    for (int it = 4; it < SEG + 4; ++it) {
        step_load(it);
        step_ab(it);
        step_out(it);
    }
}

extern "C" void kernel_launch(void* const* d_in, const int* in_sizes, int n_in,
                              void* d_out, int out_size) {
    const float* I = (const float*)d_in[0];   // input
    const float* P = (const float*)d_in[1];   // guide
    float* O = (float*)d_out;
    guided_filter_kernel<<<NBLOCK, WARPS_PER_BLOCK * 32>>>(I, P, O);
}

// round 3
// speedup vs baseline: 1.0270x; 1.0270x over previous
#include <cuda_runtime.h>

#define FULL_MASK 0xFFFFFFFFu

constexpr int H = 512;
constexpr int W = 512;
constexpr int NPLANE = 8 * 16;          // 128 independent (B,C) planes
constexpr int STRIP_OUT = 28;           // useful output columns per 32-lane warp
constexpr int NSTRIP = (W + STRIP_OUT - 1) / STRIP_OUT;   // 19
constexpr int SEG = 128;                // output rows per warp task
constexpr int NSEG = H / SEG;           // 4
constexpr int WARPS_PER_BLOCK = 4;
constexpr int NTASK = NPLANE * NSTRIP * NSEG;             // 9728
constexpr int NBLOCK = NTASK / WARPS_PER_BLOCK;           // 2432

__global__ void __launch_bounds__(WARPS_PER_BLOCK * 32)
guided_filter_kernel(const float* __restrict__ gI,
                     const float* __restrict__ gP,
                     float* __restrict__ gO)
{
    const int lane = threadIdx.x & 31;
    const int task = blockIdx.x * WARPS_PER_BLOCK + (threadIdx.x >> 5);

    const int pl  = task / (NSTRIP * NSEG);
    const int rem = task - pl * (NSTRIP * NSEG);
    const int sx  = rem / NSEG;
    const int sy  = rem - sx * NSEG;

    // Global column for this lane (lanes 0..1 and 30..31 are halo)
    const int x = sx * STRIP_OUT - 2 + lane;
    const bool xin = ((unsigned)x < (unsigned)W);

    const size_t pbase = (size_t)pl * (size_t)(H * W);
    const float* baseI = gI + pbase;
    const float* baseP = gP + pbase;
    float*       baseO = gO + pbase;

    // Horizontal window count (count_include_pad=False): 3 interior, 2 at edges
    const float cxf  = (x >= 1 && x <= W - 2) ? 3.0f : 2.0f;
    const float inv3 = 1.0f / (3.0f * cxf);
    const float inv2 = 1.0f / (2.0f * cxf);

    const int r0 = sy * SEG;

    // Register rings, period 3, index 2 = newest row.
    float hI0 = 0.f, hI1 = 0.f, hI2 = 0.f;
    float hP0 = 0.f, hP1 = 0.f, hP2 = 0.f;
    float hII0 = 0.f, hII1 = 0.f, hII2 = 0.f;
    float hIP0 = 0.f, hIP1 = 0.f, hIP2 = 0.f;
    float hA0 = 0.f, hA1 = 0.f, hA2 = 0.f;
    float hB0 = 0.f, hB1 = 0.f, hB2 = 0.f;
    float I0 = 0.f, I1 = 0.f, I2 = 0.f;

    // Prefetched values for the row about to be consumed (software pipeline).
    float nIv = 0.f, nPv = 0.f;

    auto fetch_row = [&](int y, float& oI, float& oP) {
        float Iv = 0.f, Pv = 0.f;
        if (xin && (unsigned)y < (unsigned)H) {
            const size_t off = (size_t)y * W + x;
            Iv = __ldg(baseI + off);
            Pv = __ldg(baseP + off);
        }
        oI = Iv; oP = Pv;
    };

    // step 1: consume prefetched row y, issue prefetch for y+1 FIRST,
    // then build horizontal 1x3 sums from the already-arrived data.
    auto step_load = [&](int it) {
        const float Iv = nIv, Pv = nPv;
        fetch_row(r0 - 2 + it + 1, nIv, nPv);   // prefetch next row (latency overlapped)

        hI0 = hI1;  hI1 = hI2;
        hP0 = hP1;  hP1 = hP2;
        hII0 = hII1; hII1 = hII2;
        hIP0 = hIP1; hIP1 = hIP2;
        I0 = I1; I1 = I2;

        const float Il = __shfl_up_sync(FULL_MASK, Iv, 1);
        const float Ir = __shfl_down_sync(FULL_MASK, Iv, 1);
        const float Pl = __shfl_up_sync(FULL_MASK, Pv, 1);
        const float Pr = __shfl_down_sync(FULL_MASK, Pv, 1);
        hI2  = Il + Iv + Ir;
        hP2  = Pl + Pv + Pr;
        hII2 = Il * Il + Iv * Iv + Ir * Ir;
        hIP2 = Il * Pl + Iv * Pv + Ir * Pr;
        I2 = Iv;
    };

    // step 2: 3x3 means at row y-1 -> a,b and their horizontal 1x3 sums
    auto step_ab = [&](int it) {
        const int ry = (r0 - 2 + it) - 1;
        const float invc = (ry >= 1 && ry <= H - 2) ? inv3 : inv2;
        const float mI  = (hI0  + hI1  + hI2 ) * invc;
        const float mP  = (hP0  + hP1  + hP2 ) * invc;
        const float mII = (hII0 + hII1 + hII2) * invc;
        const float mIP = (hIP0 + hIP1 + hIP2) * invc;
        const float varI = mII - mI * mI;
        const float cov  = mIP - mI * mP;
        float a = __fdividef(cov, varI + 0.01f);
        float b = mP - a * mI;
        // out-of-image positions contribute ZERO to the a/b blur
        if (!(xin && (unsigned)ry < (unsigned)H)) { a = 0.f; b = 0.f; }
        const float al = __shfl_up_sync(FULL_MASK, a, 1);
        const float ar = __shfl_down_sync(FULL_MASK, a, 1);
        const float bl = __shfl_up_sync(FULL_MASK, b, 1);
        const float br = __shfl_down_sync(FULL_MASK, b, 1);
        hA0 = hA1; hA1 = hA2;
        hB0 = hB1; hB1 = hB2;
        hA2 = al + a + ar;
        hB2 = bl + b + br;
    };

    // step 3: 3x3 blur of a,b at row y-2, write output
    auto step_out = [&](int it) {
        const int ro = (r0 - 2 + it) - 2;
        const float invo = (ro >= 1 && ro <= H - 2) ? inv3 : inv2;
        const float mA = (hA0 + hA1 + hA2) * invo;
        const float mB = (hB0 + hB1 + hB2) * invo;
        const float o = mA * I0 + mB;     // I0 holds raw I at row ro
        if (lane >= 2 && lane <= 29 && x < W) {
            baseO[(size_t)ro * W + x] = o;
        }
    };

    // Prime the prefetch register with the first row, then run the pipeline.
    fetch_row(r0 - 2, nIv, nPv);
#pragma unroll
    for (int it = 0; it < 4; ++it) {
        step_load(it);
        if (it >= 2) step_ab(it);
    }
    // steady state: unroll 3 matches ring period -> rotation via renaming
#pragma unroll 3
    for (int it = 4; it < SEG + 4; ++it) {
        step_load(it);
        step_ab(it);
        step_out(it);
    }
}

extern "C" void kernel_launch(void* const* d_in, const int* in_sizes, int n_in,
                              void* d_out, int out_size) {
    const float* I = (const float*)d_in[0];   // input
    const float* P = (const float*)d_in[1];   // guide
    float* O = (float*)d_out;
    guided_filter_kernel<<<NBLOCK, WARPS_PER_BLOCK * 32>>>(I, P, O);
}